// round 15
// baseline (speedup 1.0000x reference)
#include <cuda_runtime.h>
#include <cstddef>

// Problem constants (fixed by the reference)
#define BB 2
#define SS 2048
#define DD 1024
#define HH 16
#define DEPTH 64
#define CHUNK 128
#define NC (SS / CHUNK)            // 16 chunks
#define PITCH (DEPTH + 1)          // 65  : pad to kill smem bank conflicts
#define APITCH (CHUNK + 1)         // 129 : pad for the A (QK^T) tile
#define NTOK (BB * SS)             // 4096 rows in every GEMM

// ---------------------------------------------------------------------------
// Scratch (device globals: allocation-free per harness rules)
// ---------------------------------------------------------------------------
__device__ float g_Q[BB * SS * DD];                         // leaky(q*mask @ Wq + bq)
__device__ float g_Kp[BB * SS * DD];                        // leaky(k*mask @ Wk + bk)
__device__ float g_Vp[BB * SS * DD];                        // v*mask @ Wv + bv
__device__ float g_attn[BB * SS * DD];                      // attention output (head-concat layout)
__device__ float g_cS[BB * HH * NC * DEPTH * DEPTH];        // per-chunk K^T V -> exclusive prefix (in-place)
__device__ float g_cZ[BB * HH * NC * DEPTH];                // per-chunk sum(k) -> exclusive prefix (in-place)

// ---------------------------------------------------------------------------
// SGEMM: C[4096,1024] = (A .* rowmask) @ W[1024,1024] + bias, optional leaky.
// 128x128 block tile, BK=8, 256 threads, 8x8 register tile, vectorized.
// ---------------------------------------------------------------------------
__device__ __forceinline__ void sgemm_body(
    const float* __restrict__ A, const float* __restrict__ W,
    const float* __restrict__ bias, const float* __restrict__ rowmask,
    float* __restrict__ C, int leaky)
{
    constexpr int Kdim = 1024, Ndim = 1024;
    constexpr int BM = 128, BN = 128, BK = 8;
    __shared__ float As[BK * BM];   // stored transposed: As[k][m]
    __shared__ float Bs[BK * BN];   // Bs[k][n]

    const int tid  = threadIdx.x;       // 256 threads
    const int aRow = tid >> 1;          // 0..127
    const int aCol = (tid & 1) << 2;    // 0 or 4
    const int bRow = tid >> 5;          // 0..7
    const int bCol = (tid & 31) << 2;   // 0..124 step 4
    const int ty   = tid >> 4;          // 0..15
    const int tx   = tid & 15;          // 0..15

    const float* Ap = A + (size_t)(blockIdx.y * BM + aRow) * Kdim + aCol;
    const float* Wp = W + (size_t)bRow * Ndim + blockIdx.x * BN + bCol;
    const float  m  = rowmask ? rowmask[blockIdx.y * BM + aRow] : 1.0f;

    float acc[8][8];
#pragma unroll
    for (int i = 0; i < 8; i++)
#pragma unroll
        for (int j = 0; j < 8; j++) acc[i][j] = 0.f;

    for (int kt = 0; kt < Kdim; kt += BK) {
        float4 a4 = *(const float4*)(Ap + kt);
        As[(aCol + 0) * BM + aRow] = a4.x * m;
        As[(aCol + 1) * BM + aRow] = a4.y * m;
        As[(aCol + 2) * BM + aRow] = a4.z * m;
        As[(aCol + 3) * BM + aRow] = a4.w * m;
        *(float4*)(&Bs[bRow * BN + bCol]) = *(const float4*)(Wp + (size_t)kt * Ndim);
        __syncthreads();
#pragma unroll
        for (int kk = 0; kk < BK; kk++) {
            float ra[8], rb[8];
            *(float4*)(&ra[0]) = *(const float4*)(&As[kk * BM + ty * 8]);
            *(float4*)(&ra[4]) = *(const float4*)(&As[kk * BM + ty * 8 + 4]);
            *(float4*)(&rb[0]) = *(const float4*)(&Bs[kk * BN + tx * 8]);
            *(float4*)(&rb[4]) = *(const float4*)(&Bs[kk * BN + tx * 8 + 4]);
#pragma unroll
            for (int i = 0; i < 8; i++)
#pragma unroll
                for (int j = 0; j < 8; j++)
                    acc[i][j] += ra[i] * rb[j];
        }
        __syncthreads();
    }

    const int cRow = blockIdx.y * BM + ty * 8;
    const int cCol = blockIdx.x * BN + tx * 8;
    float breg[8];
    *(float4*)(&breg[0]) = *(const float4*)(bias + cCol);
    *(float4*)(&breg[4]) = *(const float4*)(bias + cCol + 4);
#pragma unroll
    for (int i = 0; i < 8; i++) {
        float o[8];
#pragma unroll
        for (int j = 0; j < 8; j++) {
            float x = acc[i][j] + breg[j];
            if (leaky) x = (x >= 0.f) ? x : 0.1f * x;
            o[j] = x;
        }
        *(float4*)(C + (size_t)(cRow + i) * Ndim + cCol)     = *(float4*)(&o[0]);
        *(float4*)(C + (size_t)(cRow + i) * Ndim + cCol + 4) = *(float4*)(&o[4]);
    }
}

// Fused 3-way projection: blockIdx.z selects q/k/v. leaky on q,k only.
__global__ __launch_bounds__(256) void proj_gemm(
    const float* q, const float* k, const float* v,
    const float* qm, const float* km, const float* vm,
    const float* Wq, const float* Wk, const float* Wv,
    const float* bq, const float* bk, const float* bv)
{
    const int z = blockIdx.z;
    const float* A    = (z == 0) ? q  : (z == 1) ? k  : v;
    const float* M    = (z == 0) ? qm : (z == 1) ? km : vm;
    const float* W    = (z == 0) ? Wq : (z == 1) ? Wk : Wv;
    const float* bias = (z == 0) ? bq : (z == 1) ? bk : bv;
    float* C          = (z == 0) ? g_Q : (z == 1) ? g_Kp : g_Vp;
    sgemm_body(A, W, bias, M, C, z != 2);
}

// Final output GEMM: out = g_attn @ Wo + bo (no mask, no leaky)
__global__ __launch_bounds__(256) void out_gemm(
    const float* Wo, const float* bo, float* out)
{
    sgemm_body(g_attn, Wo, bo, nullptr, out, 0);
}

// ---------------------------------------------------------------------------
// Pass 1: per (b,h,chunk) compute S_c = K_c^T V_c  [64x64]  and  z_c = sum(K_c) [64]
// grid = B*H*NC = 512 blocks of 256 threads. dyn smem = 2 * CHUNK * PITCH floats.
// ---------------------------------------------------------------------------
__global__ __launch_bounds__(256) void chunk_sums_kernel()
{
    extern __shared__ float sh[];
    float* Ksm = sh;                    // [CHUNK][PITCH]
    float* Vsm = sh + CHUNK * PITCH;    // [CHUNK][PITCH]

    const int bid = blockIdx.x;
    const int c = bid % NC;
    const int h = (bid / NC) % HH;
    const int b = bid / (NC * HH);
    const int tid = threadIdx.x;

    const size_t base = ((size_t)(b * SS + c * CHUNK)) * DD + h * DEPTH;
    const float* Kg = g_Kp + base;
    const float* Vg = g_Vp + base;

    for (int j = tid; j < CHUNK * DEPTH; j += 256) {
        const int t = j >> 6, d = j & 63;
        Ksm[t * PITCH + d] = Kg[(size_t)t * DD + d];
        Vsm[t * PITCH + d] = Vg[(size_t)t * DD + d];
    }
    __syncthreads();

    float* outS = g_cS + (size_t)bid * DEPTH * DEPTH;
    for (int j = tid; j < DEPTH * DEPTH; j += 256) {
        const int d = j >> 6, e = j & 63;
        float s = 0.f;
#pragma unroll 8
        for (int t = 0; t < CHUNK; t++) s += Ksm[t * PITCH + d] * Vsm[t * PITCH + e];
        outS[j] = s;
    }
    if (tid < DEPTH) {
        float s = 0.f;
#pragma unroll 8
        for (int t = 0; t < CHUNK; t++) s += Ksm[t * PITCH + tid];
        g_cZ[(size_t)bid * DEPTH + tid] = s;
    }
}

// ---------------------------------------------------------------------------
// Pass 2: exclusive prefix over chunks, in-place. grid = B*H = 32 blocks.
// Each thread owns 16 of the 4096 state elements (registers), no syncs needed.
// ---------------------------------------------------------------------------
__global__ __launch_bounds__(256) void prefix_kernel()
{
    const int bh = blockIdx.x;
    const int tid = threadIdx.x;
    float acc[16];
#pragma unroll
    for (int i = 0; i < 16; i++) acc[i] = 0.f;
    float zacc = 0.f;

    float* Sbase = g_cS + (size_t)bh * NC * (DEPTH * DEPTH);
    float* Zbase = g_cZ + (size_t)bh * NC * DEPTH;
    for (int c = 0; c < NC; c++) {
        float* Sc = Sbase + (size_t)c * (DEPTH * DEPTH);
#pragma unroll
        for (int i = 0; i < 16; i++) {
            const int idx = tid + i * 256;
            const float v = Sc[idx];
            Sc[idx] = acc[i];         // exclusive prefix (state BEFORE this chunk)
            acc[i] += v;
        }
        if (tid < DEPTH) {
            const float v = Zbase[c * DEPTH + tid];
            Zbase[c * DEPTH + tid] = zacc;
            zacc += v;
        }
    }
}

// ---------------------------------------------------------------------------
// Pass 3: per (b,h,chunk) output tile.
//   A = causal_mask(Q K^T)  (inclusive diagonal)
//   den[t] = rowsum(A[t]) + Q[t].z_prev
//   out[t] = (A @ V + Q @ S_prev) / den[t]
// grid = 512 blocks of 256 threads; large dynamic smem.
// ---------------------------------------------------------------------------
__global__ __launch_bounds__(256) void attn_out_kernel()
{
    extern __shared__ float sh[];
    float* Qs  = sh;                          // [CHUNK][PITCH]
    float* Ks  = Qs  + CHUNK * PITCH;         // [CHUNK][PITCH]
    float* Vs  = Ks  + CHUNK * PITCH;         // [CHUNK][PITCH]
    float* Ssm = Vs  + CHUNK * PITCH;         // [DEPTH][PITCH]
    float* Am  = Ssm + DEPTH * PITCH;         // [CHUNK][APITCH]
    float* zs  = Am  + CHUNK * APITCH;        // [DEPTH]
    float* den = zs  + DEPTH;                 // [CHUNK]

    const int bid = blockIdx.x;
    const int c = bid % NC;
    const int h = (bid / NC) % HH;
    const int b = bid / (NC * HH);
    const int tid = threadIdx.x;

    const size_t base = ((size_t)(b * SS + c * CHUNK)) * DD + h * DEPTH;
    const float* Qg = g_Q  + base;
    const float* Kg = g_Kp + base;
    const float* Vg = g_Vp + base;

    for (int j = tid; j < CHUNK * DEPTH; j += 256) {
        const int t = j >> 6, d = j & 63;
        Qs[t * PITCH + d] = Qg[(size_t)t * DD + d];
        Ks[t * PITCH + d] = Kg[(size_t)t * DD + d];
        Vs[t * PITCH + d] = Vg[(size_t)t * DD + d];
    }
    const float* Sp = g_cS + (size_t)bid * (DEPTH * DEPTH);
    for (int j = tid; j < DEPTH * DEPTH; j += 256) {
        const int d = j >> 6, e = j & 63;
        Ssm[d * PITCH + e] = Sp[j];
    }
    if (tid < DEPTH) zs[tid] = g_cZ[(size_t)bid * DEPTH + tid];
    __syncthreads();

    // Phase A: masked Q K^T. Warp-uniform t (i varies within warp).
    for (int j = tid; j < CHUNK * CHUNK; j += 256) {
        const int t = j >> 7, i = j & 127;
        float s = 0.f;
        if (i <= t) {
#pragma unroll 16
            for (int d = 0; d < DEPTH; d++) s += Qs[t * PITCH + d] * Ks[i * PITCH + d];
        }
        Am[t * APITCH + i] = s;
    }
    __syncthreads();

    // Phase B: denominators
    if (tid < CHUNK) {
        const int t = tid;
        float s = 0.f;
        for (int i = 0; i <= t; i++) s += Am[t * APITCH + i];
#pragma unroll 16
        for (int d = 0; d < DEPTH; d++) s += Qs[t * PITCH + d] * zs[d];
        den[t] = s;
    }
    __syncthreads();

    // Phase C: outputs. e varies within warp (conflict-free via PITCH), t uniform.
    float* Og = g_attn + base;
    for (int j = tid; j < CHUNK * DEPTH; j += 256) {
        const int t = j >> 6, e = j & 63;
        float s = 0.f;
#pragma unroll 16
        for (int d = 0; d < DEPTH; d++) s += Qs[t * PITCH + d] * Ssm[d * PITCH + e];
        for (int i = 0; i <= t; i++) s += Am[t * APITCH + i] * Vs[i * PITCH + e];
        Og[(size_t)t * DD + e] = s / den[t];
    }
}

// ---------------------------------------------------------------------------
// Launch
// ---------------------------------------------------------------------------
extern "C" void kernel_launch(void* const* d_in, const int* in_sizes, int n_in,
                              void* d_out, int out_size)
{
    const float* q  = (const float*)d_in[0];
    const float* k  = (const float*)d_in[1];
    const float* v  = (const float*)d_in[2];
    const float* qm = (const float*)d_in[3];
    const float* km = (const float*)d_in[4];
    const float* vm = (const float*)d_in[5];
    const float* Wq = (const float*)d_in[6];
    const float* bq = (const float*)d_in[7];
    const float* Wk = (const float*)d_in[8];
    const float* bk = (const float*)d_in[9];
    const float* Wv = (const float*)d_in[10];
    const float* bv = (const float*)d_in[11];
    const float* Wo = (const float*)d_in[12];
    const float* bo = (const float*)d_in[13];
    float* out = (float*)d_out;

    const int CS_SMEM = 2 * CHUNK * PITCH * (int)sizeof(float);                       // 66,560 B
    const int AO_SMEM = (3 * CHUNK * PITCH + DEPTH * PITCH + CHUNK * APITCH
                         + DEPTH + CHUNK) * (int)sizeof(float);                       // 183,296 B
    cudaFuncSetAttribute(chunk_sums_kernel, cudaFuncAttributeMaxDynamicSharedMemorySize, CS_SMEM);
    cudaFuncSetAttribute(attn_out_kernel,   cudaFuncAttributeMaxDynamicSharedMemorySize, AO_SMEM);

    dim3 blk(256);
    // 1) fused q/k/v projections: grid (N/128, M/128, 3)
    proj_gemm<<<dim3(1024 / 128, NTOK / 128, 3), blk>>>(q, k, v, qm, km, vm,
                                                        Wq, Wk, Wv, bq, bk, bv);
    // 2) per-chunk K^T V and sum(k)
    chunk_sums_kernel<<<BB * HH * NC, blk, CS_SMEM>>>();
    // 3) exclusive prefix over chunks (in place)
    prefix_kernel<<<BB * HH, blk>>>();
    // 4) chunked causal linear attention output
    attn_out_kernel<<<BB * HH * NC, blk, AO_SMEM>>>();
    // 5) output projection
    out_gemm<<<dim3(1024 / 128, NTOK / 128, 1), blk>>>(Wo, bo, out);
}

// round 16
// speedup vs baseline: 1.2555x; 1.2555x over previous
#include <cuda_runtime.h>
#include <cstddef>

// Problem constants (fixed by the reference)
#define BB 2
#define SS 2048
#define DD 1024
#define HH 16
#define DEPTH 64
#define CHUNK 128
#define NC (SS / CHUNK)            // 16 chunks
#define NTOK (BB * SS)             // 4096 rows in every GEMM

#define CT 132                     // pitch for [DEPTH][CT] transposed tiles and Am rows (float4-friendly)
#define VP 68                      // pitch for Vs/Ssm/Ks rows (float4-friendly)

// ---------------------------------------------------------------------------
// Scratch (device globals: allocation-free per harness rules)
// ---------------------------------------------------------------------------
__device__ float g_Q[BB * SS * DD];                         // leaky(q*mask @ Wq + bq)
__device__ float g_Kp[BB * SS * DD];                        // leaky(k*mask @ Wk + bk)
__device__ float g_Vp[BB * SS * DD];                        // v*mask @ Wv + bv
__device__ float g_attn[BB * SS * DD];                      // attention output (head-concat layout)
__device__ float g_cS[BB * HH * NC * DEPTH * DEPTH];        // per-chunk K^T V -> exclusive prefix (in-place)
__device__ float g_cZ[BB * HH * NC * DEPTH];                // per-chunk sum(k) -> exclusive prefix (in-place)

// ---------------------------------------------------------------------------
// SGEMM: C[4096,1024] = (A .* rowmask) @ W[1024,1024] + bias, optional leaky.
// 128x128 block tile, BK=16, 256 threads, 8x8 register tile, vectorized,
// global-load register prefetch to overlap LDG with compute.
// ---------------------------------------------------------------------------
__device__ __forceinline__ void sgemm_body(
    const float* __restrict__ A, const float* __restrict__ W,
    const float* __restrict__ bias, const float* __restrict__ rowmask,
    float* __restrict__ C, int leaky)
{
    constexpr int Kdim = 1024, Ndim = 1024;
    constexpr int BM = 128, BN = 128, BK = 16;
    __shared__ float As[BK * BM];   // stored transposed: As[k][m]
    __shared__ float Bs[BK * BN];   // Bs[k][n]

    const int tid  = threadIdx.x;       // 256 threads
    const int aRow = tid >> 1;          // 0..127
    const int aCol = (tid & 1) << 3;    // 0 or 8
    const int bRow = tid >> 4;          // 0..15
    const int bCol = (tid & 15) << 3;   // 0..120 step 8
    const int ty   = tid >> 4;          // 0..15
    const int tx   = tid & 15;          // 0..15

    const float* Ap = A + (size_t)(blockIdx.y * BM + aRow) * Kdim + aCol;
    const float* Wp = W + (size_t)bRow * Ndim + blockIdx.x * BN + bCol;
    const float  m  = rowmask ? rowmask[blockIdx.y * BM + aRow] : 1.0f;

    float acc[8][8];
#pragma unroll
    for (int i = 0; i < 8; i++)
#pragma unroll
        for (int j = 0; j < 8; j++) acc[i][j] = 0.f;

    // prefetch first K-slice into registers
    float4 a0 = *(const float4*)(Ap);
    float4 a1 = *(const float4*)(Ap + 4);
    float4 b0 = *(const float4*)(Wp);
    float4 b1 = *(const float4*)(Wp + 4);

    for (int kt = 0; kt < Kdim; kt += BK) {
        As[(aCol + 0) * BM + aRow] = a0.x * m;
        As[(aCol + 1) * BM + aRow] = a0.y * m;
        As[(aCol + 2) * BM + aRow] = a0.z * m;
        As[(aCol + 3) * BM + aRow] = a0.w * m;
        As[(aCol + 4) * BM + aRow] = a1.x * m;
        As[(aCol + 5) * BM + aRow] = a1.y * m;
        As[(aCol + 6) * BM + aRow] = a1.z * m;
        As[(aCol + 7) * BM + aRow] = a1.w * m;
        *(float4*)(&Bs[bRow * BN + bCol])     = b0;
        *(float4*)(&Bs[bRow * BN + bCol + 4]) = b1;
        __syncthreads();

        if (kt + BK < Kdim) {
            a0 = *(const float4*)(Ap + kt + BK);
            a1 = *(const float4*)(Ap + kt + BK + 4);
            b0 = *(const float4*)(Wp + (size_t)(kt + BK) * Ndim);
            b1 = *(const float4*)(Wp + (size_t)(kt + BK) * Ndim + 4);
        }

#pragma unroll
        for (int kk = 0; kk < BK; kk++) {
            float ra[8], rb[8];
            *(float4*)(&ra[0]) = *(const float4*)(&As[kk * BM + ty * 8]);
            *(float4*)(&ra[4]) = *(const float4*)(&As[kk * BM + ty * 8 + 4]);
            *(float4*)(&rb[0]) = *(const float4*)(&Bs[kk * BN + tx * 8]);
            *(float4*)(&rb[4]) = *(const float4*)(&Bs[kk * BN + tx * 8 + 4]);
#pragma unroll
            for (int i = 0; i < 8; i++)
#pragma unroll
                for (int j = 0; j < 8; j++)
                    acc[i][j] += ra[i] * rb[j];
        }
        __syncthreads();
    }

    const int cRow = blockIdx.y * BM + ty * 8;
    const int cCol = blockIdx.x * BN + tx * 8;
    float breg[8];
    *(float4*)(&breg[0]) = *(const float4*)(bias + cCol);
    *(float4*)(&breg[4]) = *(const float4*)(bias + cCol + 4);
#pragma unroll
    for (int i = 0; i < 8; i++) {
        float o[8];
#pragma unroll
        for (int j = 0; j < 8; j++) {
            float x = acc[i][j] + breg[j];
            if (leaky) x = (x >= 0.f) ? x : 0.1f * x;
            o[j] = x;
        }
        *(float4*)(C + (size_t)(cRow + i) * Ndim + cCol)     = *(float4*)(&o[0]);
        *(float4*)(C + (size_t)(cRow + i) * Ndim + cCol + 4) = *(float4*)(&o[4]);
    }
}

// Fused 3-way projection: blockIdx.z selects q/k/v. leaky on q,k only.
__global__ __launch_bounds__(256) void proj_gemm(
    const float* q, const float* k, const float* v,
    const float* qm, const float* km, const float* vm,
    const float* Wq, const float* Wk, const float* Wv,
    const float* bq, const float* bk, const float* bv)
{
    const int z = blockIdx.z;
    const float* A    = (z == 0) ? q  : (z == 1) ? k  : v;
    const float* M    = (z == 0) ? qm : (z == 1) ? km : vm;
    const float* W    = (z == 0) ? Wq : (z == 1) ? Wk : Wv;
    const float* bias = (z == 0) ? bq : (z == 1) ? bk : bv;
    float* C          = (z == 0) ? g_Q : (z == 1) ? g_Kp : g_Vp;
    sgemm_body(A, W, bias, M, C, z != 2);
}

// Final output GEMM: out = g_attn @ Wo + bo (no mask, no leaky)
__global__ __launch_bounds__(256) void out_gemm(
    const float* Wo, const float* bo, float* out)
{
    sgemm_body(g_attn, Wo, bo, nullptr, out, 0);
}

// ---------------------------------------------------------------------------
// Pass 1: per (b,h,chunk) compute S_c = K_c^T V_c [64x64] and z_c = sum(K_c) [64]
// Register-tiled: 256 threads, 4x4 outputs each. z fused into the main loop.
// ---------------------------------------------------------------------------
__global__ __launch_bounds__(256) void chunk_sums_kernel()
{
    extern __shared__ float sh[];
    float* Ksm = sh;                    // [CHUNK][VP]  K[t][d]
    float* Vsm = sh + CHUNK * VP;       // [CHUNK][VP]  V[t][e]

    const int bid = blockIdx.x;
    const int c = bid % NC;
    const int h = (bid / NC) % HH;
    const int b = bid / (NC * HH);
    const int tid = threadIdx.x;
    const int ty = tid >> 4;            // d-tile: rows 4*ty
    const int tx = tid & 15;            // e-tile: cols 4*tx

    const size_t base = ((size_t)(b * SS + c * CHUNK)) * DD + h * DEPTH;
    const float* Kg = g_Kp + base;
    const float* Vg = g_Vp + base;

    for (int j = tid; j < CHUNK * DEPTH; j += 256) {
        const int t = j >> 6, d = j & 63;
        Ksm[t * VP + d] = Kg[(size_t)t * DD + d];
        Vsm[t * VP + d] = Vg[(size_t)t * DD + d];
    }
    __syncthreads();

    const int d0 = ty * 4, e0 = tx * 4;
    float acc[4][4];
#pragma unroll
    for (int i = 0; i < 4; i++)
#pragma unroll
        for (int j = 0; j < 4; j++) acc[i][j] = 0.f;
    float4 z4 = make_float4(0.f, 0.f, 0.f, 0.f);

    for (int t = 0; t < CHUNK; t++) {
        float4 a4 = *(const float4*)(&Ksm[t * VP + d0]);
        float4 b4 = *(const float4*)(&Vsm[t * VP + e0]);
        acc[0][0] += a4.x * b4.x; acc[0][1] += a4.x * b4.y; acc[0][2] += a4.x * b4.z; acc[0][3] += a4.x * b4.w;
        acc[1][0] += a4.y * b4.x; acc[1][1] += a4.y * b4.y; acc[1][2] += a4.y * b4.z; acc[1][3] += a4.y * b4.w;
        acc[2][0] += a4.z * b4.x; acc[2][1] += a4.z * b4.y; acc[2][2] += a4.z * b4.z; acc[2][3] += a4.z * b4.w;
        acc[3][0] += a4.w * b4.x; acc[3][1] += a4.w * b4.y; acc[3][2] += a4.w * b4.z; acc[3][3] += a4.w * b4.w;
        if (tx == 0) { z4.x += a4.x; z4.y += a4.y; z4.z += a4.z; z4.w += a4.w; }
    }

    float* outS = g_cS + (size_t)bid * DEPTH * DEPTH;
#pragma unroll
    for (int i = 0; i < 4; i++)
        *(float4*)(outS + (d0 + i) * DEPTH + e0) = *(float4*)(&acc[i][0]);
    if (tx == 0)
        *(float4*)(g_cZ + (size_t)bid * DEPTH + d0) = z4;
}

// ---------------------------------------------------------------------------
// Pass 2: exclusive prefix over chunks, in-place. grid = B*H = 32 blocks.
// ---------------------------------------------------------------------------
__global__ __launch_bounds__(256) void prefix_kernel()
{
    const int bh = blockIdx.x;
    const int tid = threadIdx.x;
    float acc[16];
#pragma unroll
    for (int i = 0; i < 16; i++) acc[i] = 0.f;
    float zacc = 0.f;

    float* Sbase = g_cS + (size_t)bh * NC * (DEPTH * DEPTH);
    float* Zbase = g_cZ + (size_t)bh * NC * DEPTH;
    for (int c = 0; c < NC; c++) {
        float* Sc = Sbase + (size_t)c * (DEPTH * DEPTH);
#pragma unroll
        for (int i = 0; i < 16; i++) {
            const int idx = tid + i * 256;
            const float v = Sc[idx];
            Sc[idx] = acc[i];         // exclusive prefix (state BEFORE this chunk)
            acc[i] += v;
        }
        if (tid < DEPTH) {
            const float v = Zbase[c * DEPTH + tid];
            Zbase[c * DEPTH + tid] = zacc;
            zacc += v;
        }
    }
}

// ---------------------------------------------------------------------------
// Pass 3: per (b,h,chunk) output tile, register-tiled.
//   Am[t][i] = (i<=t) ? Q[t].K[i] : 0          (Phase A, 8x8 per thread)
//   den[t]   = rowsum(Am[t]) + Q[t].z_prev     (Phase B)
//   out[t]   = (Q @ S_prev + Am @ V) / den[t]  (Phase C, 8x4 per thread)
// ---------------------------------------------------------------------------
__global__ __launch_bounds__(256) void attn_out_kernel()
{
    extern __shared__ float sh[];
    float* QsT = sh;                          // [DEPTH][CT] : QsT[d*CT + t]
    float* KsT = QsT + DEPTH * CT;            // [DEPTH][CT]
    float* Vs  = KsT + DEPTH * CT;            // [CHUNK][VP] : Vs[i*VP + e]
    float* Ssm = Vs  + CHUNK * VP;            // [DEPTH][VP] : Ssm[d*VP + e]
    float* Am  = Ssm + DEPTH * VP;            // [CHUNK][CT] : Am[t*CT + i]
    float* zs  = Am  + CHUNK * CT;            // [DEPTH]
    float* den = zs  + DEPTH;                 // [CHUNK]

    const int bid = blockIdx.x;
    const int c = bid % NC;
    const int h = (bid / NC) % HH;
    const int b = bid / (NC * HH);
    const int tid = threadIdx.x;
    const int ty = tid >> 4;                  // 0..15
    const int tx = tid & 15;                  // 0..15

    const size_t base = ((size_t)(b * SS + c * CHUNK)) * DD + h * DEPTH;

    for (int j = tid; j < CHUNK * DEPTH; j += 256) {
        const int t = j >> 6, d = j & 63;
        QsT[d * CT + t] = g_Q[base + (size_t)t * DD + d];
        KsT[d * CT + t] = g_Kp[base + (size_t)t * DD + d];
        Vs[t * VP + d]  = g_Vp[base + (size_t)t * DD + d];
    }
    const float* Sp = g_cS + (size_t)bid * (DEPTH * DEPTH);
    for (int j = tid; j < DEPTH * DEPTH; j += 256) {
        const int d = j >> 6, e = j & 63;
        Ssm[d * VP + e] = Sp[j];
    }
    if (tid < DEPTH) zs[tid] = g_cZ[(size_t)bid * DEPTH + tid];
    __syncthreads();

    // ---- Phase A: masked Q K^T (8x8 register tile per thread) ----
    {
        const int t0 = ty * 8, i0 = tx * 8;
        float acc[8][8];
#pragma unroll
        for (int r = 0; r < 8; r++)
#pragma unroll
            for (int q = 0; q < 8; q++) acc[r][q] = 0.f;

        for (int d = 0; d < DEPTH; d++) {
            float ra[8], rb[8];
            *(float4*)(&ra[0]) = *(const float4*)(&QsT[d * CT + t0]);
            *(float4*)(&ra[4]) = *(const float4*)(&QsT[d * CT + t0 + 4]);
            *(float4*)(&rb[0]) = *(const float4*)(&KsT[d * CT + i0]);
            *(float4*)(&rb[4]) = *(const float4*)(&KsT[d * CT + i0 + 4]);
#pragma unroll
            for (int r = 0; r < 8; r++)
#pragma unroll
                for (int q = 0; q < 8; q++)
                    acc[r][q] += ra[r] * rb[q];
        }
        // masked write (zeros above the diagonal so Phase B/C loop uniformly)
#pragma unroll
        for (int r = 0; r < 8; r++) {
            const int t = t0 + r;
            float o[8];
#pragma unroll
            for (int q = 0; q < 8; q++) o[q] = (i0 + q <= t) ? acc[r][q] : 0.f;
            *(float4*)(&Am[t * CT + i0])     = *(float4*)(&o[0]);
            *(float4*)(&Am[t * CT + i0 + 4]) = *(float4*)(&o[4]);
        }
    }
    __syncthreads();

    // ---- Phase B: denominators ----
    if (tid < CHUNK) {
        const int t = tid;
        float s = 0.f;
#pragma unroll 8
        for (int i = 0; i < CHUNK; i++) s += Am[t * CT + i];
#pragma unroll 8
        for (int d = 0; d < DEPTH; d++) s += QsT[d * CT + t] * zs[d];
        den[t] = s;
    }
    __syncthreads();

    // ---- Phase C: out = (Q @ S_prev + Am @ V) / den  (8x4 register tile) ----
    {
        const int t0 = ty * 8, e0 = tx * 4;
        float acc[8][4];
#pragma unroll
        for (int r = 0; r < 8; r++)
#pragma unroll
            for (int q = 0; q < 4; q++) acc[r][q] = 0.f;

        // Q @ S_prev
        for (int d = 0; d < DEPTH; d++) {
            float ra[8];
            *(float4*)(&ra[0]) = *(const float4*)(&QsT[d * CT + t0]);
            *(float4*)(&ra[4]) = *(const float4*)(&QsT[d * CT + t0 + 4]);
            float4 b4 = *(const float4*)(&Ssm[d * VP + e0]);
#pragma unroll
            for (int r = 0; r < 8; r++) {
                acc[r][0] += ra[r] * b4.x; acc[r][1] += ra[r] * b4.y;
                acc[r][2] += ra[r] * b4.z; acc[r][3] += ra[r] * b4.w;
            }
        }
        // Am @ V, i unrolled by 4 with float4 A-row loads
        for (int i = 0; i < CHUNK; i += 4) {
            float4 av[8];
#pragma unroll
            for (int r = 0; r < 8; r++)
                av[r] = *(const float4*)(&Am[(t0 + r) * CT + i]);
#pragma unroll
            for (int s = 0; s < 4; s++) {
                float4 b4 = *(const float4*)(&Vs[(i + s) * VP + e0]);
#pragma unroll
                for (int r = 0; r < 8; r++) {
                    const float a = (s == 0) ? av[r].x : (s == 1) ? av[r].y
                                  : (s == 2) ? av[r].z : av[r].w;
                    acc[r][0] += a * b4.x; acc[r][1] += a * b4.y;
                    acc[r][2] += a * b4.z; acc[r][3] += a * b4.w;
                }
            }
        }
        // divide by den, store
        float* Og = g_attn + base;
#pragma unroll
        for (int r = 0; r < 8; r++) {
            const float inv = 1.0f / den[t0 + r];
            float4 o4 = make_float4(acc[r][0] * inv, acc[r][1] * inv,
                                    acc[r][2] * inv, acc[r][3] * inv);
            *(float4*)(Og + (size_t)(t0 + r) * DD + e0) = o4;
        }
    }
}

// ---------------------------------------------------------------------------
// Launch
// ---------------------------------------------------------------------------
extern "C" void kernel_launch(void* const* d_in, const int* in_sizes, int n_in,
                              void* d_out, int out_size)
{
    const float* q  = (const float*)d_in[0];
    const float* k  = (const float*)d_in[1];
    const float* v  = (const float*)d_in[2];
    const float* qm = (const float*)d_in[3];
    const float* km = (const float*)d_in[4];
    const float* vm = (const float*)d_in[5];
    const float* Wq = (const float*)d_in[6];
    const float* bq = (const float*)d_in[7];
    const float* Wk = (const float*)d_in[8];
    const float* bk = (const float*)d_in[9];
    const float* Wv = (const float*)d_in[10];
    const float* bv = (const float*)d_in[11];
    const float* Wo = (const float*)d_in[12];
    const float* bo = (const float*)d_in[13];
    float* out = (float*)d_out;

    const int CS_SMEM = 2 * CHUNK * VP * (int)sizeof(float);                          // 69,632 B
    const int AO_SMEM = (2 * DEPTH * CT + CHUNK * VP + DEPTH * VP + CHUNK * CT
                         + DEPTH + CHUNK) * (int)sizeof(float);                       // 188,160 B
    cudaFuncSetAttribute(chunk_sums_kernel, cudaFuncAttributeMaxDynamicSharedMemorySize, CS_SMEM);
    cudaFuncSetAttribute(attn_out_kernel,   cudaFuncAttributeMaxDynamicSharedMemorySize, AO_SMEM);

    dim3 blk(256);
    // 1) fused q/k/v projections: grid (N/128, M/128, 3)
    proj_gemm<<<dim3(1024 / 128, NTOK / 128, 3), blk>>>(q, k, v, qm, km, vm,
                                                        Wq, Wk, Wv, bq, bk, bv);
    // 2) per-chunk K^T V and sum(k)
    chunk_sums_kernel<<<BB * HH * NC, blk, CS_SMEM>>>();
    // 3) exclusive prefix over chunks (in place)
    prefix_kernel<<<BB * HH, blk>>>();
    // 4) chunked causal linear attention output
    attn_out_kernel<<<BB * HH * NC, blk, AO_SMEM>>>();
    // 5) output projection
    out_gemm<<<dim3(1024 / 128, NTOK / 128, 1), blk>>>(Wo, bo, out);
}